// round 2
// baseline (speedup 1.0000x reference)
#include <cuda_runtime.h>
#include <stdint.h>

#define B 16
#define N 20000
#define M 128
#define NUM_CLASSES 80
#define SAMP 512
#define FG_TARGET 128
#define CAP 1024
#define NBUCKET 4096

// Scratch (no allocations allowed): matched max-IoU + argmax per proposal,
// per-group top-512 indices, per-image fg counts.
__device__ float g_mval[B * N];
__device__ int   g_midx[B * N];
__device__ int   g_top[2 * B * SAMP];
__device__ int   g_fgcnt[B];

// ---------------------------------------------------------------------------
// Kernel A: per-proposal max IoU + first-argmax over 128 GT boxes.
// GT boxes + areas staged in shared memory (broadcast reads, conflict-free).
// Arithmetic pinned with _rn intrinsics to match XLA op-for-op (no FMA
// contraction): iou = (w*h) / ((area_g + area_p) - inter).
// ---------------------------------------------------------------------------
__global__ void iou_kernel(const float* __restrict__ gt,
                           const float* __restrict__ pr) {
    __shared__ float4 sgt[M];
    __shared__ float  sarea[M];
    const int b   = blockIdx.y;
    const int tid = threadIdx.x;

    for (int m = tid; m < M; m += blockDim.x) {
        float4 g = ((const float4*)gt)[b * M + m];
        sgt[m]   = g;
        sarea[m] = __fmul_rn(__fsub_rn(g.z, g.x), __fsub_rn(g.w, g.y));
    }
    __syncthreads();

    const int n = blockIdx.x * blockDim.x + tid;
    if (n >= N) return;

    float4 p = ((const float4*)pr)[b * N + n];
    float area_p = __fmul_rn(__fsub_rn(p.z, p.x), __fsub_rn(p.w, p.y));

    float best = -1.0f;
    int   bidx = 0;
#pragma unroll 4
    for (int m = 0; m < M; m++) {
        float4 g = sgt[m];
        float lx = fmaxf(g.x, p.x);
        float ly = fmaxf(g.y, p.y);
        float rx = fminf(g.z, p.z);
        float ry = fminf(g.w, p.w);
        float w  = fmaxf(__fsub_rn(rx, lx), 0.0f);
        float h  = fmaxf(__fsub_rn(ry, ly), 0.0f);
        float inter = __fmul_rn(w, h);
        float denom = __fsub_rn(__fadd_rn(sarea[m], area_p), inter);
        float iou   = __fdiv_rn(inter, denom);
        if (iou > best) { best = iou; bidx = m; }  // strict > == first argmax
    }
    g_mval[b * N + n] = best;
    g_midx[b * N + n] = bidx;
}

// ---------------------------------------------------------------------------
// Kernel B: per (group, image) stable top-512 by (key, index).
// grid = (2, B): blockIdx.x==0 -> fg (mval>=0.5), ==1 -> bg. 1024 threads.
//   1. 4096-bin histogram of keys (keys ~ U[0,1), bin = floor(key*4096))
//   2. block scan -> first bin where cumulative >= min(512, total)
//   3. gather candidates (bin <= T) as 64-bit composite (key_bits<<32)|idx
//   4. bitonic sort 1024 candidates in smem -> exact stable argsort prefix
// ---------------------------------------------------------------------------
__global__ void __launch_bounds__(1024, 1)
select_kernel(const float* __restrict__ keys) {
    const int g   = blockIdx.x;          // 0 = fg, 1 = bg
    const int b   = blockIdx.y;
    const bool wantFg = (g == 0);
    const int tid = threadIdx.x;

    __shared__ unsigned hist[NBUCKET];
    __shared__ unsigned wsum[32];
    __shared__ int      sT;
    __shared__ unsigned sTotal, sCnt;
    __shared__ unsigned long long cand[CAP];

    for (int i = tid; i < NBUCKET; i += 1024) hist[i] = 0;
    if (tid == 0) { sT = -1; sCnt = 0; sTotal = 0; }
    __syncthreads();

    const float* kb = keys   + (size_t)b * N;
    const float* mb = g_mval + (size_t)b * N;

    // Pass 1: histogram
    for (int n = tid; n < N; n += 1024) {
        bool fg = mb[n] >= 0.5f;
        if (fg == wantFg) {
            int bu = (int)(kb[n] * (float)NBUCKET);
            bu = min(max(bu, 0), NBUCKET - 1);
            atomicAdd(&hist[bu], 1u);
        }
    }
    __syncthreads();

    // Block scan over 4096 bins (4 per thread)
    unsigned v0 = hist[4 * tid + 0], v1 = hist[4 * tid + 1];
    unsigned v2 = hist[4 * tid + 2], v3 = hist[4 * tid + 3];
    unsigned s   = v0 + v1 + v2 + v3;
    unsigned inc = s;
    for (int d = 1; d < 32; d <<= 1) {
        unsigned o = __shfl_up_sync(0xFFFFFFFFu, inc, d);
        if ((tid & 31) >= d) inc += o;
    }
    if ((tid & 31) == 31) wsum[tid >> 5] = inc;
    __syncthreads();
    if (tid < 32) {
        unsigned w  = wsum[tid];
        unsigned wi = w;
        for (int d = 1; d < 32; d <<= 1) {
            unsigned o = __shfl_up_sync(0xFFFFFFFFu, wi, d);
            if (tid >= d) wi += o;
        }
        wsum[tid] = wi - w;                 // exclusive warp offsets
        if (tid == 31) sTotal = wi;         // group population
    }
    __syncthreads();

    unsigned excl   = inc - s + wsum[tid >> 5];
    unsigned total  = sTotal;
    unsigned target = min((unsigned)SAMP, total);
    if (target > 0) {
        unsigned cum = excl;
        unsigned vv[4] = {v0, v1, v2, v3};
#pragma unroll
        for (int i = 0; i < 4; i++) {
            unsigned nb = vv[i];
            if (cum < target && cum + nb >= target) sT = 4 * tid + i;
            cum += nb;
        }
    }
    __syncthreads();

    // Pass 2: gather candidates from bins <= T
    const int T = sT;
    for (int n = tid; n < N; n += 1024) {
        bool fg = mb[n] >= 0.5f;
        if (fg == wantFg) {
            float k = kb[n];
            int bu = (int)(k * (float)NBUCKET);
            bu = min(max(bu, 0), NBUCKET - 1);
            if (bu <= T) {
                unsigned p = atomicAdd(&sCnt, 1u);
                if (p < CAP)
                    cand[p] = ((unsigned long long)__float_as_uint(k) << 32)
                              | (unsigned)n;
            }
        }
    }
    __syncthreads();

    unsigned C = min(sCnt, (unsigned)CAP);
    if (tid >= (int)C) cand[tid] = ~0ull;   // pad

    // Bitonic sort CAP=1024 elements, 1 element/thread
    for (int k2 = 2; k2 <= CAP; k2 <<= 1) {
        for (int j = k2 >> 1; j > 0; j >>= 1) {
            __syncthreads();
            int ixj = tid ^ j;
            if (ixj > tid) {
                unsigned long long a = cand[tid];
                unsigned long long c = cand[ixj];
                bool asc = ((tid & k2) == 0);
                if ((a > c) == asc) { cand[tid] = c; cand[ixj] = a; }
            }
        }
    }
    __syncthreads();

    if (tid < SAMP)
        g_top[(g * B + b) * SAMP + tid] = (int)(cand[tid] & 0xFFFFFFFFull);
    if (g == 0 && tid == 0) g_fgcnt[b] = (int)total;
}

// ---------------------------------------------------------------------------
// Kernel C: final merge + gather. Output layout (all float32, concatenated):
//   [0 : 16*512*5)            float_out = {iou, gt_box xyxy}
//   [40960 : 40960 + 16*512)  sampled_classes
//   [49152 : 49152 + 16*512)  sampled_idxs
// ---------------------------------------------------------------------------
__global__ void gather_kernel(const float* __restrict__ gt_boxes,
                              const int*   __restrict__ gt_classes,
                              float* __restrict__ out) {
    const int b = blockIdx.x;
    const int i = threadIdx.x;   // 0..511

    int fg_take = min(FG_TARGET, g_fgcnt[b]);
    int sel = (i < fg_take) ? g_top[(0 * B + b) * SAMP + i]
                            : g_top[(1 * B + b) * SAMP + (i - fg_take)];

    float mval = g_mval[b * N + sel];
    int   midx = g_midx[b * N + sel];
    int   cls  = (mval >= 0.5f) ? gt_classes[b * M + midx] : NUM_CLASSES;
    float4 box = ((const float4*)gt_boxes)[b * M + midx];

    float* fo = out + ((size_t)b * SAMP + i) * 5;
    fo[0] = mval; fo[1] = box.x; fo[2] = box.y; fo[3] = box.z; fo[4] = box.w;

    out[(size_t)B * SAMP * 5 + b * SAMP + i]               = (float)cls;
    out[(size_t)B * SAMP * 5 + B * SAMP + b * SAMP + i]    = (float)sel;
}

extern "C" void kernel_launch(void* const* d_in, const int* in_sizes, int n_in,
                              void* d_out, int out_size) {
    const float* gt_boxes   = (const float*)d_in[0];
    const int*   gt_classes = (const int*)  d_in[1];
    const float* proposals  = (const float*)d_in[2];
    const float* keys       = (const float*)d_in[3];

    dim3 gridA((N + 255) / 256, B);
    iou_kernel<<<gridA, 256>>>(gt_boxes, proposals);

    dim3 gridB(2, B);
    select_kernel<<<gridB, 1024>>>(keys);

    gather_kernel<<<B, SAMP>>>(gt_boxes, gt_classes, (float*)d_out);
}

// round 4
// speedup vs baseline: 2.1279x; 2.1279x over previous
#include <cuda_runtime.h>
#include <stdint.h>

#define B 16
#define N 20000
#define M 128
#define NUM_CLASSES 80
#define SAMP 512
#define FG_TARGET 128
#define CAP 1024
#define NBUCKET 4096
#define NSTRIPE 64          // 16px stripes over [0,1024)
#define INV_STRIPE 0.0625f  // 1/16

__device__ float g_mval[B * N];
__device__ int   g_midx[B * N];
__device__ int   g_top[2 * B * SAMP];
__device__ int   g_fgcnt[B];

__device__ __forceinline__ int stripe_clamp(float x) {
    int s = (int)(x * INV_STRIPE);          // trunc == floor for x >= 0
    return min(NSTRIPE - 1, max(0, s));
}

// ---------------------------------------------------------------------------
// Kernel A: per-proposal max IoU + first-argmax over 128 GT boxes, with
// spatial pruning. Per image, each block builds 64-stripe x/y interval
// bitmasks (128 bits each) over the GT boxes; a proposal ORs masks of its
// covered stripes per axis, ANDs them, and evaluates full IoU only for the
// ~3 surviving GT candidates (ascending m => first-argmax preserved; all
// pruned pairs have iou == 0 which can never beat best=0/bidx=0).
// IoU arithmetic pinned with _rn intrinsics to match XLA op-for-op.
// ---------------------------------------------------------------------------
__global__ void iou_kernel(const float* __restrict__ gt,
                           const float* __restrict__ pr) {
    __shared__ float4 sgt[M];
    __shared__ float  sarea[M];
    __shared__ unsigned long long smx[NSTRIPE][2];   // 128 words
    __shared__ unsigned long long smy[NSTRIPE][2];   // 128 words
    const int b   = blockIdx.y;
    const int tid = threadIdx.x;

    // zero masks (256 words, 256 threads)
    {
        unsigned long long* flat = &smx[0][0];       // smx then smy contiguous
        if (tid < 128) flat[tid] = 0ull;
        else           (&smy[0][0])[tid - 128] = 0ull;
    }
    __syncthreads();

    // build GT tiles + stripe masks (threads 0..127, one GT each)
    if (tid < M) {
        float4 g = ((const float4*)gt)[b * M + tid];
        sgt[tid]   = g;
        sarea[tid] = __fmul_rn(__fsub_rn(g.z, g.x), __fsub_rn(g.w, g.y));
        unsigned long long bit = 1ull << (tid & 63);
        int w = tid >> 6;
        int x0 = stripe_clamp(g.x), x1 = stripe_clamp(g.z);
        for (int s = x0; s <= x1; s++) atomicOr(&smx[s][w], bit);
        int y0 = stripe_clamp(g.y), y1 = stripe_clamp(g.w);
        for (int s = y0; s <= y1; s++) atomicOr(&smy[s][w], bit);
    }
    __syncthreads();

    const int n = blockIdx.x * blockDim.x + tid;
    if (n >= N) return;

    float4 p = ((const float4*)pr)[b * N + n];
    float area_p = __fmul_rn(__fsub_rn(p.z, p.x), __fsub_rn(p.w, p.y));

    // candidate mask = (union of x-stripe masks) & (union of y-stripe masks)
    unsigned long long mx0 = 0, mx1 = 0, my0 = 0, my1 = 0;
    {
        int s0 = stripe_clamp(p.x), s1 = stripe_clamp(p.z);
        for (int s = s0; s <= s1; s++) { mx0 |= smx[s][0]; mx1 |= smx[s][1]; }
        int t0 = stripe_clamp(p.y), t1 = stripe_clamp(p.w);
        for (int s = t0; s <= t1; s++) { my0 |= smy[s][0]; my1 |= smy[s][1]; }
    }
    unsigned long long c0 = mx0 & my0;
    unsigned long long c1 = mx1 & my1;

    float best = 0.0f;   // all-pruned => argmax of all-zeros = index 0
    int   bidx = 0;

#pragma unroll
    for (int word = 0; word < 2; word++) {
        unsigned long long mask = (word == 0) ? c0 : c1;
        int base = word << 6;
        while (mask) {
            int m = base + (__ffsll((long long)mask) - 1);
            mask &= mask - 1;
            float4 g = sgt[m];
            float lx = fmaxf(g.x, p.x);
            float ly = fmaxf(g.y, p.y);
            float rx = fminf(g.z, p.z);
            float ry = fminf(g.w, p.w);
            float w  = fmaxf(__fsub_rn(rx, lx), 0.0f);
            float h  = fmaxf(__fsub_rn(ry, ly), 0.0f);
            float inter = __fmul_rn(w, h);
            float denom = __fsub_rn(__fadd_rn(sarea[m], area_p), inter);
            float iou   = __fdiv_rn(inter, denom);
            if (iou > best) { best = iou; bidx = m; }  // strict > : first argmax
        }
    }
    g_mval[b * N + n] = best;
    g_midx[b * N + n] = bidx;
}

// ---------------------------------------------------------------------------
// Kernel B: per (group, image) stable top-512 by (key, index).
// grid = (2, B): blockIdx.x==0 -> fg (mval>=0.5), ==1 -> bg. 1024 threads.
//   1. 4096-bin histogram of keys (keys ~ U[0,1))
//   2. block scan -> first bin where cumulative >= min(512, total)
//   3. gather candidates (bin <= T) as 64-bit composite (key_bits<<32)|idx
//   4. bitonic sort 1024 candidates in smem -> exact stable argsort prefix
// ---------------------------------------------------------------------------
__global__ void __launch_bounds__(1024, 1)
select_kernel(const float* __restrict__ keys) {
    const int g   = blockIdx.x;          // 0 = fg, 1 = bg
    const int b   = blockIdx.y;
    const bool wantFg = (g == 0);
    const int tid = threadIdx.x;

    __shared__ unsigned hist[NBUCKET];
    __shared__ unsigned wsum[32];
    __shared__ int      sT;
    __shared__ unsigned sTotal, sCnt;
    __shared__ unsigned long long cand[CAP];

    for (int i = tid; i < NBUCKET; i += 1024) hist[i] = 0;
    if (tid == 0) { sT = -1; sCnt = 0; sTotal = 0; }
    __syncthreads();

    const float* kb = keys   + (size_t)b * N;
    const float* mb = g_mval + (size_t)b * N;

    for (int n = tid; n < N; n += 1024) {
        bool fg = mb[n] >= 0.5f;
        if (fg == wantFg) {
            int bu = (int)(kb[n] * (float)NBUCKET);
            bu = min(max(bu, 0), NBUCKET - 1);
            atomicAdd(&hist[bu], 1u);
        }
    }
    __syncthreads();

    unsigned v0 = hist[4 * tid + 0], v1 = hist[4 * tid + 1];
    unsigned v2 = hist[4 * tid + 2], v3 = hist[4 * tid + 3];
    unsigned s   = v0 + v1 + v2 + v3;
    unsigned inc = s;
    for (int d = 1; d < 32; d <<= 1) {
        unsigned o = __shfl_up_sync(0xFFFFFFFFu, inc, d);
        if ((tid & 31) >= d) inc += o;
    }
    if ((tid & 31) == 31) wsum[tid >> 5] = inc;
    __syncthreads();
    if (tid < 32) {
        unsigned w  = wsum[tid];
        unsigned wi = w;
        for (int d = 1; d < 32; d <<= 1) {
            unsigned o = __shfl_up_sync(0xFFFFFFFFu, wi, d);
            if (tid >= d) wi += o;
        }
        wsum[tid] = wi - w;
        if (tid == 31) sTotal = wi;
    }
    __syncthreads();

    unsigned excl   = inc - s + wsum[tid >> 5];
    unsigned total  = sTotal;
    unsigned target = min((unsigned)SAMP, total);
    if (target > 0) {
        unsigned cum = excl;
        unsigned vv[4] = {v0, v1, v2, v3};
#pragma unroll
        for (int i = 0; i < 4; i++) {
            unsigned nb = vv[i];
            if (cum < target && cum + nb >= target) sT = 4 * tid + i;
            cum += nb;
        }
    }
    __syncthreads();

    const int T = sT;
    for (int n = tid; n < N; n += 1024) {
        bool fg = mb[n] >= 0.5f;
        if (fg == wantFg) {
            float k = kb[n];
            int bu = (int)(k * (float)NBUCKET);
            bu = min(max(bu, 0), NBUCKET - 1);
            if (bu <= T) {
                unsigned p = atomicAdd(&sCnt, 1u);
                if (p < CAP)
                    cand[p] = ((unsigned long long)__float_as_uint(k) << 32)
                              | (unsigned)n;
            }
        }
    }
    __syncthreads();

    unsigned C = min(sCnt, (unsigned)CAP);
    if (tid >= (int)C) cand[tid] = ~0ull;

    for (int k2 = 2; k2 <= CAP; k2 <<= 1) {
        for (int j = k2 >> 1; j > 0; j >>= 1) {
            __syncthreads();
            int ixj = tid ^ j;
            if (ixj > tid) {
                unsigned long long a = cand[tid];
                unsigned long long c = cand[ixj];
                bool asc = ((tid & k2) == 0);
                if ((a > c) == asc) { cand[tid] = c; cand[ixj] = a; }
            }
        }
    }
    __syncthreads();

    if (tid < SAMP)
        g_top[(g * B + b) * SAMP + tid] = (int)(cand[tid] & 0xFFFFFFFFull);
    if (g == 0 && tid == 0) g_fgcnt[b] = (int)total;
}

// ---------------------------------------------------------------------------
// Kernel C: final merge + gather. Output layout (all float32, concatenated):
//   [0 : 16*512*5) float_out, then classes [16*512], then idxs [16*512].
// ---------------------------------------------------------------------------
__global__ void gather_kernel(const float* __restrict__ gt_boxes,
                              const int*   __restrict__ gt_classes,
                              float* __restrict__ out) {
    const int b = blockIdx.x;
    const int i = threadIdx.x;   // 0..511

    int fg_take = min(FG_TARGET, g_fgcnt[b]);
    int sel = (i < fg_take) ? g_top[(0 * B + b) * SAMP + i]
                            : g_top[(1 * B + b) * SAMP + (i - fg_take)];

    float mval = g_mval[b * N + sel];
    int   midx = g_midx[b * N + sel];
    int   cls  = (mval >= 0.5f) ? gt_classes[b * M + midx] : NUM_CLASSES;
    float4 box = ((const float4*)gt_boxes)[b * M + midx];

    float* fo = out + ((size_t)b * SAMP + i) * 5;
    fo[0] = mval; fo[1] = box.x; fo[2] = box.y; fo[3] = box.z; fo[4] = box.w;

    out[(size_t)B * SAMP * 5 + b * SAMP + i]            = (float)cls;
    out[(size_t)B * SAMP * 5 + B * SAMP + b * SAMP + i] = (float)sel;
}

extern "C" void kernel_launch(void* const* d_in, const int* in_sizes, int n_in,
                              void* d_out, int out_size) {
    const float* gt_boxes   = (const float*)d_in[0];
    const int*   gt_classes = (const int*)  d_in[1];
    const float* proposals  = (const float*)d_in[2];
    const float* keys       = (const float*)d_in[3];

    dim3 gridA((N + 255) / 256, B);
    iou_kernel<<<gridA, 256>>>(gt_boxes, proposals);

    dim3 gridB(2, B);
    select_kernel<<<gridB, 1024>>>(keys);

    gather_kernel<<<B, SAMP>>>(gt_boxes, gt_classes, (float*)d_out);
}

// round 5
// speedup vs baseline: 2.3096x; 1.0854x over previous
#include <cuda_runtime.h>
#include <stdint.h>

#define B 16
#define N 20000
#define M 128
#define NWORDS 625            // N/32 exactly
#define NUM_CLASSES 80
#define SAMP 512
#define FG_TARGET 128
#define CAP 1024
#define NBUCKET 4096
#define SPEC_BIN 176          // speculative gather bound ~0.043 (real T ~ bin 105)
#define NSTRIPE 64            // 16px stripes over [0,1024)
#define INV_STRIPE 0.0625f
#define NLVL 7                // sparse-table levels: ranges up to 64 stripes

typedef unsigned long long ull;

__device__ float    g_mval[B * N];
__device__ int      g_midx[B * N];
__device__ unsigned g_fgbit[B * NWORDS];
__device__ int      g_top[2 * B * SAMP];
__device__ int      g_fgcnt[B];

__device__ __forceinline__ int stripe_clamp(float x) {
    int s = (int)(x * INV_STRIPE);          // trunc == floor for x >= 0; neg -> clamps
    return min(NSTRIPE - 1, max(0, s));
}

// ---------------------------------------------------------------------------
// Kernel A: per-proposal max IoU + first-argmax over 128 GT boxes, with
// sparse-table spatial pruning. Per image: 64-stripe x/y 128-bit interval
// masks, expanded into a 7-level sparse table so the union over any stripe
// range is OR of exactly two 16B entries. Candidate mask = x-union & y-union;
// full IoU evaluated only for surviving bits (ascending m preserves first-
// argmax; pruned pairs have iou==0 which never beats best=0/bidx=0).
// IoU arithmetic pinned with _rn intrinsics to match XLA op-for-op.
// Also emits per-warp ballot bitmask of (iou >= 0.5) for the select kernel.
// ---------------------------------------------------------------------------
__global__ void iou_kernel(const float* __restrict__ gt,
                           const float* __restrict__ pr) {
    __shared__ float4 sgt[M];
    __shared__ float  sarea[M];
    __shared__ __align__(16) ull stab[2][NLVL][NSTRIPE][2];
    const int b   = blockIdx.y;
    const int tid = threadIdx.x;

    // zero level 0 (2 axes * 64 stripes * 2 words = 256 words, 256 threads)
    {
        int ax = tid >> 7, r = tid & 127;
        stab[ax][0][r >> 1][r & 1] = 0ull;
    }
    __syncthreads();

    // GT tiles + level-0 stripe masks (threads 0..127, one GT each)
    if (tid < M) {
        float4 g = ((const float4*)gt)[b * M + tid];
        sgt[tid]   = g;
        sarea[tid] = __fmul_rn(__fsub_rn(g.z, g.x), __fsub_rn(g.w, g.y));
        ull bit = 1ull << (tid & 63);
        int w = tid >> 6;
        int x0 = stripe_clamp(g.x), x1 = stripe_clamp(g.z);
        for (int s = x0; s <= x1; s++) atomicOr(&stab[0][0][s][w], bit);
        int y0 = stripe_clamp(g.y), y1 = stripe_clamp(g.w);
        for (int s = y0; s <= y1; s++) atomicOr(&stab[1][0][s][w], bit);
    }
    __syncthreads();

    // build sparse table levels 1..6 (all 256 threads, 1 word each)
    for (int l = 1; l < NLVL; l++) {
        int ax = tid >> 7, r = tid & 127, s = r >> 1, w = r & 1;
        int o = min(s + (1 << (l - 1)), NSTRIPE - 1);
        stab[ax][l][s][w] = stab[ax][l - 1][s][w] | stab[ax][l - 1][o][w];
        __syncthreads();
    }

    const int n = blockIdx.x * blockDim.x + tid;
    if (n >= N) return;   // warps are fully in- or out-of-range (N % 32 == 0)

    float4 p = ((const float4*)pr)[b * N + n];
    float area_p = __fmul_rn(__fsub_rn(p.z, p.x), __fsub_rn(p.w, p.y));

    ull c0 = 0, c1 = 0;
    {
        ull mx0 = 0, mx1 = 0, my0 = 0, my1 = 0;
        int s0 = stripe_clamp(p.x), s1 = stripe_clamp(p.z);
        if (s1 >= s0) {
            int k = 31 - __clz(s1 - s0 + 1);
            ulonglong2 a  = *(const ulonglong2*)&stab[0][k][s0][0];
            ulonglong2 bb = *(const ulonglong2*)&stab[0][k][s1 - (1 << k) + 1][0];
            mx0 = a.x | bb.x; mx1 = a.y | bb.y;
        }
        int t0 = stripe_clamp(p.y), t1 = stripe_clamp(p.w);
        if (t1 >= t0) {
            int k = 31 - __clz(t1 - t0 + 1);
            ulonglong2 a  = *(const ulonglong2*)&stab[1][k][t0][0];
            ulonglong2 bb = *(const ulonglong2*)&stab[1][k][t1 - (1 << k) + 1][0];
            my0 = a.x | bb.x; my1 = a.y | bb.y;
        }
        c0 = mx0 & my0; c1 = mx1 & my1;
    }

    float best = 0.0f;   // all-pruned => argmax of all-zeros = index 0
    int   bidx = 0;
#pragma unroll
    for (int word = 0; word < 2; word++) {
        ull mask = (word == 0) ? c0 : c1;
        int base = word << 6;
        while (mask) {
            int m = base + (__ffsll((long long)mask) - 1);
            mask &= mask - 1;
            float4 g = sgt[m];
            float lx = fmaxf(g.x, p.x);
            float ly = fmaxf(g.y, p.y);
            float rx = fminf(g.z, p.z);
            float ry = fminf(g.w, p.w);
            float w  = fmaxf(__fsub_rn(rx, lx), 0.0f);
            float h  = fmaxf(__fsub_rn(ry, ly), 0.0f);
            float inter = __fmul_rn(w, h);
            float denom = __fsub_rn(__fadd_rn(sarea[m], area_p), inter);
            float iou   = __fdiv_rn(inter, denom);
            if (iou > best) { best = iou; bidx = m; }  // strict > : first argmax
        }
    }
    g_mval[b * N + n] = best;
    g_midx[b * N + n] = bidx;

    unsigned bal = __ballot_sync(0xFFFFFFFFu, best >= 0.5f);
    if ((tid & 31) == 0) g_fgbit[b * NWORDS + (n >> 5)] = bal;
}

// ---------------------------------------------------------------------------
// Kernel B: per (group, image) stable top-512 by (key, index).
// grid = (2, B): blockIdx.x==0 -> fg, ==1 -> bg. 1024 threads.
// Totals from popc of the fg bitmask (no mval read). If total <= CAP:
// single-pass gather of ALL members (fg typical), else histogram with
// speculative gather (bucket <= SPEC_BIN) in the same pass; exact fallback
// pass only if speculation insufficient. Bitonic sort of next-pow2(C).
// ---------------------------------------------------------------------------
__global__ void __launch_bounds__(1024, 1)
select_kernel(const float* __restrict__ keys) {
    const int g   = blockIdx.x;          // 0 = fg, 1 = bg
    const int b   = blockIdx.y;
    const bool wantFg = (g == 0);
    const int tid = threadIdx.x;

    __shared__ unsigned hist[NBUCKET];
    __shared__ unsigned wsum[32];
    __shared__ unsigned sRed[32];
    __shared__ int      sT;
    __shared__ unsigned sTotal, sCnt;
    __shared__ ull      cand[CAP];

    const unsigned* fgw = g_fgbit + b * NWORDS;
    const float*    kb  = keys + (size_t)b * N;

    // group total via popc (N == NWORDS*32 exactly, no partial word)
    unsigned loc = 0;
    for (int i = tid; i < NWORDS; i += 1024) {
        unsigned w = fgw[i];
        loc += __popc(wantFg ? w : ~w);
    }
    for (int d = 16; d; d >>= 1) loc += __shfl_down_sync(0xFFFFFFFFu, loc, d);
    if ((tid & 31) == 0) sRed[tid >> 5] = loc;
    if (tid == 0) { sCnt = 0; sT = -1; }
    __syncthreads();
    if (tid < 32) {
        unsigned v = sRed[tid];
        for (int d = 16; d; d >>= 1) v += __shfl_down_sync(0xFFFFFFFFu, v, d);
        if (tid == 0) sTotal = v;
    }
    __syncthreads();

    const unsigned total  = sTotal;
    const unsigned target = min((unsigned)SAMP, total);
    unsigned C;

    if (total <= CAP) {
        // gather everything in one pass; sort gives exact stable order
        for (int n = tid; n < N; n += 1024) {
            unsigned w = fgw[n >> 5];
            if (((w >> (n & 31)) & 1u) == (wantFg ? 1u : 0u)) {
                unsigned p = atomicAdd(&sCnt, 1u);
                if (p < CAP)
                    cand[p] = ((ull)__float_as_uint(kb[n]) << 32) | (unsigned)n;
            }
        }
        __syncthreads();
        C = total;
    } else {
        for (int i = tid; i < NBUCKET; i += 1024) hist[i] = 0;
        __syncthreads();

        // pass 1: histogram + speculative gather
        for (int n = tid; n < N; n += 1024) {
            unsigned w = fgw[n >> 5];
            if (((w >> (n & 31)) & 1u) == (wantFg ? 1u : 0u)) {
                float k = kb[n];
                int bu = min(max((int)(k * (float)NBUCKET), 0), NBUCKET - 1);
                atomicAdd(&hist[bu], 1u);
                if (bu <= SPEC_BIN) {
                    unsigned p = atomicAdd(&sCnt, 1u);
                    if (p < CAP)
                        cand[p] = ((ull)__float_as_uint(k) << 32) | (unsigned)n;
                }
            }
        }
        __syncthreads();

        // block scan over 4096 bins -> threshold bin T
        unsigned v0 = hist[4 * tid + 0], v1 = hist[4 * tid + 1];
        unsigned v2 = hist[4 * tid + 2], v3 = hist[4 * tid + 3];
        unsigned s   = v0 + v1 + v2 + v3;
        unsigned inc = s;
        for (int d = 1; d < 32; d <<= 1) {
            unsigned o = __shfl_up_sync(0xFFFFFFFFu, inc, d);
            if ((tid & 31) >= d) inc += o;
        }
        if ((tid & 31) == 31) wsum[tid >> 5] = inc;
        __syncthreads();
        if (tid < 32) {
            unsigned w  = wsum[tid];
            unsigned wi = w;
            for (int d = 1; d < 32; d <<= 1) {
                unsigned o = __shfl_up_sync(0xFFFFFFFFu, wi, d);
                if (tid >= d) wi += o;
            }
            wsum[tid] = wi - w;
        }
        __syncthreads();
        unsigned excl = inc - s + wsum[tid >> 5];
        {
            unsigned cum = excl;
            unsigned vv[4] = {v0, v1, v2, v3};
#pragma unroll
            for (int i = 0; i < 4; i++) {
                unsigned nb = vv[i];
                if (cum < target && cum + nb >= target) sT = 4 * tid + i;
                cum += nb;
            }
        }
        __syncthreads();

        const int T = sT;
        if (T > SPEC_BIN || sCnt > CAP) {
            // speculation failed (statistically ~never): exact fallback pass
            __syncthreads();
            if (tid == 0) sCnt = 0;
            __syncthreads();
            for (int n = tid; n < N; n += 1024) {
                unsigned w = fgw[n >> 5];
                if (((w >> (n & 31)) & 1u) == (wantFg ? 1u : 0u)) {
                    float k = kb[n];
                    int bu = min(max((int)(k * (float)NBUCKET), 0), NBUCKET - 1);
                    if (bu <= T) {
                        unsigned p = atomicAdd(&sCnt, 1u);
                        if (p < CAP)
                            cand[p] = ((ull)__float_as_uint(k) << 32) | (unsigned)n;
                    }
                }
            }
            __syncthreads();
        }
        C = min(sCnt, (unsigned)CAP);
    }

    // pad to next pow2 and bitonic sort (only P threads compare; all barrier)
    unsigned P = (C <= 1) ? 1u : (1u << (32 - __clz(C - 1)));
    for (int i = tid; i < (int)P; i += 1024)
        if (i >= (int)C) cand[i] = ~0ull;
    __syncthreads();

    for (unsigned k2 = 2; k2 <= P; k2 <<= 1) {
        for (unsigned j = k2 >> 1; j > 0; j >>= 1) {
            if (tid < (int)P) {
                int ixj = tid ^ (int)j;
                if (ixj > tid) {
                    ull a = cand[tid];
                    ull c = cand[ixj];
                    bool asc = ((tid & k2) == 0);
                    if ((a > c) == asc) { cand[tid] = c; cand[ixj] = a; }
                }
            }
            __syncthreads();
        }
    }

    if (tid < (int)target)
        g_top[(g * B + b) * SAMP + tid] = (int)(cand[tid] & 0xFFFFFFFFull);
    if (g == 0 && tid == 0) g_fgcnt[b] = (int)total;
}

// ---------------------------------------------------------------------------
// Kernel C: final merge + gather. Output layout (all float32, concatenated):
//   [0 : 16*512*5) float_out, then classes [16*512], then idxs [16*512].
// ---------------------------------------------------------------------------
__global__ void gather_kernel(const float* __restrict__ gt_boxes,
                              const int*   __restrict__ gt_classes,
                              float* __restrict__ out) {
    const int b = blockIdx.x;
    const int i = threadIdx.x;   // 0..511

    int fg_take = min(FG_TARGET, g_fgcnt[b]);
    int sel = (i < fg_take) ? g_top[(0 * B + b) * SAMP + i]
                            : g_top[(1 * B + b) * SAMP + (i - fg_take)];

    float mval = g_mval[b * N + sel];
    int   midx = g_midx[b * N + sel];
    int   cls  = (mval >= 0.5f) ? gt_classes[b * M + midx] : NUM_CLASSES;
    float4 box = ((const float4*)gt_boxes)[b * M + midx];

    float* fo = out + ((size_t)b * SAMP + i) * 5;
    fo[0] = mval; fo[1] = box.x; fo[2] = box.y; fo[3] = box.z; fo[4] = box.w;

    out[(size_t)B * SAMP * 5 + b * SAMP + i]            = (float)cls;
    out[(size_t)B * SAMP * 5 + B * SAMP + b * SAMP + i] = (float)sel;
}

extern "C" void kernel_launch(void* const* d_in, const int* in_sizes, int n_in,
                              void* d_out, int out_size) {
    const float* gt_boxes   = (const float*)d_in[0];
    const int*   gt_classes = (const int*)  d_in[1];
    const float* proposals  = (const float*)d_in[2];
    const float* keys       = (const float*)d_in[3];

    dim3 gridA((N + 255) / 256, B);
    iou_kernel<<<gridA, 256>>>(gt_boxes, proposals);

    dim3 gridB(2, B);
    select_kernel<<<gridB, 1024>>>(keys);

    gather_kernel<<<B, SAMP>>>(gt_boxes, gt_classes, (float*)d_out);
}

// round 7
// speedup vs baseline: 2.6051x; 1.1279x over previous
#include <cuda_runtime.h>
#include <stdint.h>

#define B 16
#define N 20000
#define M 128
#define NWORDS 625            // N/32 exactly
#define NUM_CLASSES 80
#define SAMP 512
#define FG_TARGET 128
#define CAP 1024
#define NBUCKET 4096
#define NSTRIPE 64            // 16px stripes over [0,1024)
#define INV_STRIPE 0.0625f
#define NLVL 7
#define PROPS_PER_THREAD 4
#define IOU_THREADS 256
#define PROPS_PER_BLOCK (PROPS_PER_THREAD * IOU_THREADS)   // 1024

typedef unsigned long long ull;

__device__ float    g_mval[B * N];
__device__ int      g_midx[B * N];
__device__ unsigned g_fgbit[B * NWORDS];
__device__ unsigned g_hist[B * 2 * NBUCKET];   // per (image, group) key-bin hist
__device__ int      g_fgcnt[B];                // atomic fg count per image
__device__ int      g_top[2 * B * SAMP];

__device__ __forceinline__ int stripe_clamp(float x) {
    int s = (int)(x * INV_STRIPE);
    return min(NSTRIPE - 1, max(0, s));
}
__device__ __forceinline__ int key_bin(float k) {
    return min(max((int)(k * (float)NBUCKET), 0), NBUCKET - 1);
}

// ---------------------------------------------------------------------------
// Kernel A: per-proposal max IoU + first-argmax over 128 GT boxes with
// sparse-table spatial pruning; 4 proposals per thread (single resident wave,
// preamble amortized). Emits: mval/midx, fg ballot bitmask, atomic fg count,
// and per-(image,group) global key-bin histograms for the select kernel.
// IoU arithmetic pinned with _rn intrinsics to match XLA op-for-op.
// ---------------------------------------------------------------------------
__global__ void __launch_bounds__(IOU_THREADS)
iou_kernel(const float* __restrict__ gt,
           const float* __restrict__ pr,
           const float* __restrict__ keys) {
    __shared__ float4 sgt[M];
    __shared__ float  sarea[M];
    __shared__ __align__(16) ull stab[2][NLVL][NSTRIPE][2];
    const int b   = blockIdx.y;
    const int tid = threadIdx.x;

    {   // zero level 0 (256 words, 256 threads)
        int ax = tid >> 7, r = tid & 127;
        stab[ax][0][r >> 1][r & 1] = 0ull;
    }
    __syncthreads();

    if (tid < M) {
        float4 g = ((const float4*)gt)[b * M + tid];
        sgt[tid]   = g;
        sarea[tid] = __fmul_rn(__fsub_rn(g.z, g.x), __fsub_rn(g.w, g.y));
        ull bit = 1ull << (tid & 63);
        int w = tid >> 6;
        int x0 = stripe_clamp(g.x), x1 = stripe_clamp(g.z);
        for (int s = x0; s <= x1; s++) atomicOr(&stab[0][0][s][w], bit);
        int y0 = stripe_clamp(g.y), y1 = stripe_clamp(g.w);
        for (int s = y0; s <= y1; s++) atomicOr(&stab[1][0][s][w], bit);
    }
    __syncthreads();

    for (int l = 1; l < NLVL; l++) {
        int ax = tid >> 7, r = tid & 127, s = r >> 1, w = r & 1;
        int o = min(s + (1 << (l - 1)), NSTRIPE - 1);
        stab[ax][l][s][w] = stab[ax][l - 1][s][w] | stab[ax][l - 1][o][w];
        __syncthreads();
    }

    const int base = blockIdx.x * PROPS_PER_BLOCK;

    for (int it = 0; it < PROPS_PER_THREAD; it++) {
        const int n = base + it * IOU_THREADS + tid;
        if (n >= N) break;    // warp-uniform (all boundaries multiple of 32)

        float4 p = ((const float4*)pr)[b * N + n];
        float   k = keys[(size_t)b * N + n];
        float area_p = __fmul_rn(__fsub_rn(p.z, p.x), __fsub_rn(p.w, p.y));

        ull c0 = 0, c1 = 0;
        {
            ull mx0 = 0, mx1 = 0, my0 = 0, my1 = 0;
            int s0 = stripe_clamp(p.x), s1 = stripe_clamp(p.z);
            if (s1 >= s0) {
                int kk = 31 - __clz(s1 - s0 + 1);
                ulonglong2 a  = *(const ulonglong2*)&stab[0][kk][s0][0];
                ulonglong2 bb = *(const ulonglong2*)&stab[0][kk][s1 - (1 << kk) + 1][0];
                mx0 = a.x | bb.x; mx1 = a.y | bb.y;
            }
            int t0 = stripe_clamp(p.y), t1 = stripe_clamp(p.w);
            if (t1 >= t0) {
                int kk = 31 - __clz(t1 - t0 + 1);
                ulonglong2 a  = *(const ulonglong2*)&stab[1][kk][t0][0];
                ulonglong2 bb = *(const ulonglong2*)&stab[1][kk][t1 - (1 << kk) + 1][0];
                my0 = a.x | bb.x; my1 = a.y | bb.y;
            }
            c0 = mx0 & my0; c1 = mx1 & my1;
        }

        float best = 0.0f;   // all-pruned => argmax of all-zeros = index 0
        int   bidx = 0;
#pragma unroll
        for (int word = 0; word < 2; word++) {
            ull mask = (word == 0) ? c0 : c1;
            int mbase = word << 6;
            while (mask) {
                int m = mbase + (__ffsll((long long)mask) - 1);
                mask &= mask - 1;
                float4 g = sgt[m];
                float lx = fmaxf(g.x, p.x);
                float ly = fmaxf(g.y, p.y);
                float rx = fminf(g.z, p.z);
                float ry = fminf(g.w, p.w);
                float w  = fmaxf(__fsub_rn(rx, lx), 0.0f);
                float h  = fmaxf(__fsub_rn(ry, ly), 0.0f);
                float inter = __fmul_rn(w, h);
                float denom = __fsub_rn(__fadd_rn(sarea[m], area_p), inter);
                float iou   = __fdiv_rn(inter, denom);
                if (iou > best) { best = iou; bidx = m; }   // first argmax
            }
        }
        g_mval[b * N + n] = best;
        g_midx[b * N + n] = bidx;

        bool fg = best >= 0.5f;
        atomicAdd(&g_hist[((b << 1) | (fg ? 0 : 1)) * NBUCKET + key_bin(k)], 1u);

        unsigned bal = __ballot_sync(0xFFFFFFFFu, fg);
        if ((tid & 31) == 0) {
            g_fgbit[b * NWORDS + (n >> 5)] = bal;
            if (bal) atomicAdd(&g_fgcnt[b], __popc(bal));
        }
    }
}

// ---------------------------------------------------------------------------
// warp-level 32-lane bitonic sort (ascending) of 64-bit composite keys
// ---------------------------------------------------------------------------
__device__ __forceinline__ ull warp_sort32(ull v, int lane) {
#pragma unroll
    for (int k = 2; k <= 32; k <<= 1) {
#pragma unroll
        for (int j = k >> 1; j > 0; j >>= 1) {
            ull o = __shfl_xor_sync(0xFFFFFFFFu, v, j);
            bool keep_min = ((lane & j) == 0) == ((lane & k) == 0);
            v = ((o < v) == keep_min) ? o : v;
        }
    }
    return v;
}

// ---------------------------------------------------------------------------
// Kernel B: per (group, image) stable top-512 by (key, index). grid (2, B).
// Totals from g_fgcnt (no counting pass). If total <= CAP: direct gather of
// all members via bitmask words + block bitonic (fg path, ~130 items).
// Else: scan the prebuilt global histogram -> exact threshold bin T ->
// counting-scatter gather into per-bin segments -> warp shfl-bitonic per bin
// (no block barriers). Fallback full bitonic if any bin > 32 items.
// ---------------------------------------------------------------------------
__global__ void __launch_bounds__(1024, 1)
select_kernel(const float* __restrict__ keys) {
    const int g   = blockIdx.x;          // 0 = fg, 1 = bg
    const int b   = blockIdx.y;
    const bool wantFg = (g == 0);
    const int tid  = threadIdx.x;
    const int lane = tid & 31;
    const int wid  = tid >> 5;

    __shared__ unsigned sstart[NBUCKET];   // per-bin segment start (prefix)
    __shared__ unsigned scur[NBUCKET];     // per-bin scatter cursor
    __shared__ unsigned wsum[32];
    __shared__ int      sT, sOver;
    __shared__ unsigned sCnt, sC;
    __shared__ ull      cand[CAP];

    const unsigned* fgw = g_fgbit + b * NWORDS;
    const float*    kb  = keys + (size_t)b * N;

    const int fgtot = g_fgcnt[b];
    const unsigned total  = wantFg ? (unsigned)fgtot : (unsigned)(N - fgtot);
    const unsigned target = min((unsigned)SAMP, total);

    if (tid == 0) { sCnt = 0; sT = -1; sOver = 0; sC = 0; }
    __syncthreads();

    unsigned C;
    bool sorted_by_bins = false;

    if (total <= CAP) {
        // direct gather: iterate bitmask words, extract members
        for (int w = tid; w < NWORDS; w += 1024) {
            unsigned bits = fgw[w];
            if (!wantFg) bits = ~bits;
            while (bits) {
                int bit = __ffs(bits) - 1;
                bits &= bits - 1;
                int n = (w << 5) + bit;
                unsigned p = atomicAdd(&sCnt, 1u);
                if (p < CAP)
                    cand[p] = ((ull)__float_as_uint(kb[n]) << 32) | (unsigned)n;
            }
        }
        __syncthreads();
        C = min(total, (unsigned)CAP);
    } else {
        // scan prebuilt histogram -> threshold bin + per-bin prefixes
        const unsigned* gh = g_hist + ((b << 1) | g) * NBUCKET;
        unsigned v0 = gh[4 * tid + 0], v1 = gh[4 * tid + 1];
        unsigned v2 = gh[4 * tid + 2], v3 = gh[4 * tid + 3];
        unsigned s   = v0 + v1 + v2 + v3;
        unsigned inc = s;
        for (int d = 1; d < 32; d <<= 1) {
            unsigned o = __shfl_up_sync(0xFFFFFFFFu, inc, d);
            if (lane >= d) inc += o;
        }
        if (lane == 31) wsum[wid] = inc;
        __syncthreads();
        if (tid < 32) {
            unsigned w  = wsum[tid];
            unsigned wi = w;
            for (int d = 1; d < 32; d <<= 1) {
                unsigned o = __shfl_up_sync(0xFFFFFFFFu, wi, d);
                if (tid >= d) wi += o;
            }
            wsum[tid] = wi - w;
        }
        __syncthreads();
        unsigned cum = inc - s + wsum[wid];
        unsigned vv[4] = {v0, v1, v2, v3};
#pragma unroll
        for (int i = 0; i < 4; i++) {
            sstart[4 * tid + i] = cum;
            scur[4 * tid + i]   = cum;
            unsigned nb = vv[i];
            if (cum < target && cum + nb >= target) { sT = 4 * tid + i; sC = cum + nb; }
            cum += nb;
        }
        __syncthreads();

        const int T = sT;
        // counting-scatter gather: members in bins <= T land in bin segments
        for (int n = tid; n < N; n += 1024) {
            unsigned w = fgw[n >> 5];
            if (((w >> (n & 31)) & 1u) == (wantFg ? 1u : 0u)) {
                float k = kb[n];
                int bu = key_bin(k);
                if (bu <= T) {
                    unsigned p = atomicAdd(&scur[bu], 1u);
                    if (p < CAP)
                        cand[p] = ((ull)__float_as_uint(k) << 32) | (unsigned)n;
                }
            }
        }
        __syncthreads();

        // per-bin warp sorts (bins <= T, ~5 items each)
        for (int bin = wid; bin <= T; bin += 32) {
            unsigned st = sstart[bin];
            unsigned cn = scur[bin] - st;
            if (cn == 0) continue;
            if (cn > 32) { if (lane == 0) sOver = 1; continue; }
            ull v = (lane < (int)cn) ? cand[st + lane] : ~0ull;
            v = warp_sort32(v, lane);
            if (lane < (int)cn) cand[st + lane] = v;
        }
        __syncthreads();

        C = min(sC, (unsigned)CAP);
        sorted_by_bins = (sOver == 0);
    }

    if (!sorted_by_bins) {
        // block bitonic over next-pow2(C)
        unsigned P = (C <= 1) ? 1u : (1u << (32 - __clz(C - 1)));
        for (int i = tid; i < (int)P; i += 1024)
            if (i >= (int)C) cand[i] = ~0ull;
        __syncthreads();
        for (unsigned k2 = 2; k2 <= P; k2 <<= 1) {
            for (unsigned j = k2 >> 1; j > 0; j >>= 1) {
                if (tid < (int)P) {
                    int ixj = tid ^ (int)j;
                    if (ixj > tid) {
                        ull a = cand[tid];
                        ull c = cand[ixj];
                        bool asc = ((tid & k2) == 0);
                        if ((a > c) == asc) { cand[tid] = c; cand[ixj] = a; }
                    }
                }
                __syncthreads();
            }
        }
    }

    if (tid < (int)target)
        g_top[(g * B + b) * SAMP + tid] = (int)(cand[tid] & 0xFFFFFFFFull);
}

// ---------------------------------------------------------------------------
// Kernel C: final merge + gather, then re-zero scratch for the next replay
// (globals are zero at module load; every launch leaves them zero again).
// Output: [0:16*512*5) float_out, then classes [16*512], then idxs [16*512].
// ---------------------------------------------------------------------------
__global__ void gather_kernel(const float* __restrict__ gt_boxes,
                              const int*   __restrict__ gt_classes,
                              float* __restrict__ out) {
    const int b = blockIdx.x;
    const int i = threadIdx.x;   // 0..511

    int fg_take = min(FG_TARGET, g_fgcnt[b]);
    int sel = (i < fg_take) ? g_top[(0 * B + b) * SAMP + i]
                            : g_top[(1 * B + b) * SAMP + (i - fg_take)];

    float mval = g_mval[b * N + sel];
    int   midx = g_midx[b * N + sel];
    int   cls  = (mval >= 0.5f) ? gt_classes[b * M + midx] : NUM_CLASSES;
    float4 box = ((const float4*)gt_boxes)[b * M + midx];

    float* fo = out + ((size_t)b * SAMP + i) * 5;
    fo[0] = mval; fo[1] = box.x; fo[2] = box.y; fo[3] = box.z; fo[4] = box.w;

    out[(size_t)B * SAMP * 5 + b * SAMP + i]            = (float)cls;
    out[(size_t)B * SAMP * 5 + B * SAMP + b * SAMP + i] = (float)sel;

    __syncthreads();   // everyone has read g_fgcnt[b] / g_top
    unsigned* h = g_hist + b * 2 * NBUCKET;
    for (int j = i; j < 2 * NBUCKET; j += SAMP) h[j] = 0;
    if (i == 0) g_fgcnt[b] = 0;
}

extern "C" void kernel_launch(void* const* d_in, const int* in_sizes, int n_in,
                              void* d_out, int out_size) {
    const float* gt_boxes   = (const float*)d_in[0];
    const int*   gt_classes = (const int*)  d_in[1];
    const float* proposals  = (const float*)d_in[2];
    const float* keys       = (const float*)d_in[3];

    dim3 gridA((N + PROPS_PER_BLOCK - 1) / PROPS_PER_BLOCK, B);
    iou_kernel<<<gridA, IOU_THREADS>>>(gt_boxes, proposals, keys);

    dim3 gridB(2, B);
    select_kernel<<<gridB, 1024>>>(keys);

    gather_kernel<<<B, SAMP>>>(gt_boxes, gt_classes, (float*)d_out);
}